// round 1
// baseline (speedup 1.0000x reference)
#include <cuda_runtime.h>
#include <math.h>

#define Bn 8
#define Sn 2048
#define En 1024
#define Hn 64

#define BM 64
#define BN 64

// Scratch for q,k,v: [B,S,H] each, fp32 (4 MB each)
__device__ float g_q[Bn * Sn * Hn];
__device__ float g_k[Bn * Sn * Hn];
__device__ float g_v[Bn * Sn * Hn];

// ---------------------------------------------------------------------------
// QKV projection: out[r, h] = sum_e x[r, e] * W[e, h] + b[h]
// M = B*S = 16384 rows, N = 64, K = 1024. grid.x = M/64, grid.y = 3 (q/k/v)
// ---------------------------------------------------------------------------
__global__ __launch_bounds__(256) void proj_kernel(
    const float* __restrict__ x,
    const float* __restrict__ Wq, const float* __restrict__ bq,
    const float* __restrict__ Wk, const float* __restrict__ bk,
    const float* __restrict__ Wv, const float* __restrict__ bv)
{
    const float* W;
    const float* bias;
    float* out;
    if (blockIdx.y == 0)      { W = Wq; bias = bq; out = g_q; }
    else if (blockIdx.y == 1) { W = Wk; bias = bk; out = g_k; }
    else                      { W = Wv; bias = bv; out = g_v; }

    __shared__ float sX[64][17];   // [m][k], padded
    __shared__ float sW[16][64];   // [k][n]

    const int tid = threadIdx.x;
    const int tx = tid & 15;
    const int ty = tid >> 4;
    const int row0 = blockIdx.x * 64;

    float acc[4][4];
    #pragma unroll
    for (int i = 0; i < 4; i++)
        #pragma unroll
        for (int j = 0; j < 4; j++) acc[i][j] = 0.0f;

    for (int k0 = 0; k0 < En; k0 += 16) {
        // Load X tile: 64 rows x 16 k, one float4 per thread
        {
            int r  = tid >> 2;   // 0..63
            int c4 = tid & 3;    // 0..3
            float4 v = *reinterpret_cast<const float4*>(
                &x[(size_t)(row0 + r) * En + k0 + c4 * 4]);
            sX[r][c4 * 4 + 0] = v.x;
            sX[r][c4 * 4 + 1] = v.y;
            sX[r][c4 * 4 + 2] = v.z;
            sX[r][c4 * 4 + 3] = v.w;
        }
        // Load W tile: 16 k x 64 n, one float4 per thread
        {
            int kk = tid >> 4;   // 0..15
            int c4 = tid & 15;   // 0..15
            float4 v = *reinterpret_cast<const float4*>(
                &W[(size_t)(k0 + kk) * Hn + c4 * 4]);
            *reinterpret_cast<float4*>(&sW[kk][c4 * 4]) = v;
        }
        __syncthreads();

        #pragma unroll
        for (int kk = 0; kk < 16; kk++) {
            float a[4], bcol[4];
            #pragma unroll
            for (int i = 0; i < 4; i++) a[i] = sX[ty + 16 * i][kk];
            #pragma unroll
            for (int j = 0; j < 4; j++) bcol[j] = sW[kk][tx + 16 * j];
            #pragma unroll
            for (int i = 0; i < 4; i++)
                #pragma unroll
                for (int j = 0; j < 4; j++)
                    acc[i][j] = fmaf(a[i], bcol[j], acc[i][j]);
        }
        __syncthreads();
    }

    #pragma unroll
    for (int i = 0; i < 4; i++) {
        int r = row0 + ty + 16 * i;
        #pragma unroll
        for (int j = 0; j < 4; j++) {
            int c = tx + 16 * j;
            out[(size_t)r * Hn + c] = acc[i][j] + bias[c];
        }
    }
}

// ---------------------------------------------------------------------------
// Flash attention (causal + pad mask), fp32.
// grid: (S/BM, B). 256 threads. Each thread owns a 4x4 register tile with
// ownership map row = ty + 16*i, col = tx + 16*j (conflict-free LDS pattern).
// ---------------------------------------------------------------------------
__global__ __launch_bounds__(256) void attn_kernel(
    const int* __restrict__ mask, float* __restrict__ out)
{
    extern __shared__ float smem[];
    float (*sQ)[Hn + 1] = (float (*)[Hn + 1])(smem);
    float (*sK)[Hn + 1] = (float (*)[Hn + 1])(smem + BM * (Hn + 1));
    float (*sV)[Hn + 1] = (float (*)[Hn + 1])(smem + 2 * BM * (Hn + 1));
    float (*sP)[BN + 1] = (float (*)[BN + 1])(smem + 3 * BM * (Hn + 1));
    int* sMask = (int*)(smem + 3 * BM * (Hn + 1) + BM * (BN + 1));

    const int b   = blockIdx.y;
    const int qt  = blockIdx.x;
    const int tid = threadIdx.x;
    const int tx  = tid & 15;
    const int ty  = tid >> 4;
    const int qbase = qt * BM;

    const float* qp = g_q + (size_t)b * Sn * Hn;
    const float* kp = g_k + (size_t)b * Sn * Hn;
    const float* vp = g_v + (size_t)b * Sn * Hn;

    // Load Q tile, pre-scaled by 1/sqrt(H) = 0.125
    for (int idx = tid; idx < BM * Hn / 4; idx += 256) {
        int r  = idx >> 4;
        int c4 = idx & 15;
        float4 v = *reinterpret_cast<const float4*>(
            &qp[(size_t)(qbase + r) * Hn + c4 * 4]);
        sQ[r][c4 * 4 + 0] = v.x * 0.125f;
        sQ[r][c4 * 4 + 1] = v.y * 0.125f;
        sQ[r][c4 * 4 + 2] = v.z * 0.125f;
        sQ[r][c4 * 4 + 3] = v.w * 0.125f;
    }

    float m[4], l[4], o[4][4];
    #pragma unroll
    for (int i = 0; i < 4; i++) {
        m[i] = -INFINITY;
        l[i] = 0.0f;
        #pragma unroll
        for (int j = 0; j < 4; j++) o[i][j] = 0.0f;
    }

    for (int jt = 0; jt <= qt; jt++) {
        const int kbase = jt * BN;

        // Load K, V tiles + pad mask
        for (int idx = tid; idx < BN * Hn / 4; idx += 256) {
            int r  = idx >> 4;
            int c4 = idx & 15;
            float4 kv = *reinterpret_cast<const float4*>(
                &kp[(size_t)(kbase + r) * Hn + c4 * 4]);
            sK[r][c4 * 4 + 0] = kv.x;
            sK[r][c4 * 4 + 1] = kv.y;
            sK[r][c4 * 4 + 2] = kv.z;
            sK[r][c4 * 4 + 3] = kv.w;
            float4 vv = *reinterpret_cast<const float4*>(
                &vp[(size_t)(kbase + r) * Hn + c4 * 4]);
            sV[r][c4 * 4 + 0] = vv.x;
            sV[r][c4 * 4 + 1] = vv.y;
            sV[r][c4 * 4 + 2] = vv.z;
            sV[r][c4 * 4 + 3] = vv.w;
        }
        if (tid < BN) sMask[tid] = mask[b * Sn + kbase + tid];
        __syncthreads();

        // S = Q * K^T (Q pre-scaled)
        float s[4][4];
        #pragma unroll
        for (int i = 0; i < 4; i++)
            #pragma unroll
            for (int j = 0; j < 4; j++) s[i][j] = 0.0f;

        #pragma unroll 8
        for (int kk = 0; kk < Hn; kk++) {
            float a[4], bb[4];
            #pragma unroll
            for (int i = 0; i < 4; i++) a[i] = sQ[ty + 16 * i][kk];
            #pragma unroll
            for (int j = 0; j < 4; j++) bb[j] = sK[tx + 16 * j][kk];
            #pragma unroll
            for (int i = 0; i < 4; i++)
                #pragma unroll
                for (int j = 0; j < 4; j++)
                    s[i][j] = fmaf(a[i], bb[j], s[i][j]);
        }

        // Mask + online softmax update
        #pragma unroll
        for (int i = 0; i < 4; i++) {
            const int qrow = qbase + ty + 16 * i;
            float tmax = -INFINITY;
            #pragma unroll
            for (int j = 0; j < 4; j++) {
                const int kcol = kbase + tx + 16 * j;
                const bool valid = (kcol <= qrow) && (sMask[tx + 16 * j] != 0);
                if (!valid) s[i][j] = -INFINITY;
                tmax = fmaxf(tmax, s[i][j]);
            }
            #pragma unroll
            for (int off = 8; off > 0; off >>= 1)
                tmax = fmaxf(tmax, __shfl_xor_sync(0xffffffffu, tmax, off, 16));

            const float mnew = fmaxf(m[i], tmax);
            const float alpha = (m[i] == mnew) ? 1.0f : __expf(m[i] - mnew);

            float ps = 0.0f;
            #pragma unroll
            for (int j = 0; j < 4; j++) {
                float p = (s[i][j] == -INFINITY) ? 0.0f : __expf(s[i][j] - mnew);
                sP[ty + 16 * i][tx + 16 * j] = p;
                ps += p;
            }
            #pragma unroll
            for (int off = 8; off > 0; off >>= 1)
                ps += __shfl_xor_sync(0xffffffffu, ps, off, 16);

            l[i] = l[i] * alpha + ps;
            m[i] = mnew;
            #pragma unroll
            for (int j = 0; j < 4; j++) o[i][j] *= alpha;
        }
        __syncthreads();   // sP fully written; everyone done with sK

        // O += P * V
        #pragma unroll 8
        for (int kk = 0; kk < BN; kk++) {
            float pv[4], vv[4];
            #pragma unroll
            for (int i = 0; i < 4; i++) pv[i] = sP[ty + 16 * i][kk];
            #pragma unroll
            for (int j = 0; j < 4; j++) vv[j] = sV[kk][tx + 16 * j];
            #pragma unroll
            for (int i = 0; i < 4; i++)
                #pragma unroll
                for (int j = 0; j < 4; j++)
                    o[i][j] = fmaf(pv[i], vv[j], o[i][j]);
        }
        __syncthreads();   // done reading sP/sV before next tile overwrites
    }

    // Normalize and write out
    #pragma unroll
    for (int i = 0; i < 4; i++) {
        const int r = qbase + ty + 16 * i;
        const float inv = 1.0f / l[i];
        #pragma unroll
        for (int j = 0; j < 4; j++) {
            out[((size_t)b * Sn + r) * Hn + tx + 16 * j] = o[i][j] * inv;
        }
    }
}

static const int ATTN_SMEM_BYTES =
    (3 * BM * (Hn + 1) + BM * (BN + 1)) * (int)sizeof(float) + BN * (int)sizeof(int);

extern "C" void kernel_launch(void* const* d_in, const int* in_sizes, int n_in,
                              void* d_out, int out_size)
{
    const float* x    = (const float*)d_in[0];
    const int*   mask = (const int*)d_in[1];
    const float* Wq   = (const float*)d_in[2];
    const float* bq   = (const float*)d_in[3];
    const float* Wk   = (const float*)d_in[4];
    const float* bk   = (const float*)d_in[5];
    const float* Wv   = (const float*)d_in[6];
    const float* bv   = (const float*)d_in[7];
    float* out = (float*)d_out;

    static bool attr_set = false;
    if (!attr_set) {
        cudaFuncSetAttribute(attn_kernel,
                             cudaFuncAttributeMaxDynamicSharedMemorySize,
                             ATTN_SMEM_BYTES);
        attr_set = true;
    }

    dim3 gproj(Bn * Sn / 64, 3);
    proj_kernel<<<gproj, 256>>>(x, Wq, bq, Wk, bk, Wv, bv);

    dim3 gattn(Sn / BM, Bn);
    attn_kernel<<<gattn, 256, ATTN_SMEM_BYTES>>>(mask, out);
}

// round 2
// speedup vs baseline: 1.2620x; 1.2620x over previous
#include <cuda_runtime.h>
#include <math.h>

#define Bn 8
#define Sn 2048
#define En 1024
#define Hn 64

#define BM 32
#define BN 64

// Scratch for q,k,v: [B,S,H] each, fp32 (4 MB each)
__device__ float g_q[Bn * Sn * Hn];
__device__ float g_k[Bn * Sn * Hn];
__device__ float g_v[Bn * Sn * Hn];

// ---------------------------------------------------------------------------
// QKV projection: out[r,h] = sum_e x[r,e]*W[e,h] + b[h]
// Tile: 64 rows x 64 cols, KT=64. Thread tile: 4x4 contiguous
// (rows 4*ty..+3, cols 4*tx..+3) -> all inner-loop smem traffic is LDS.128.
// XOR swizzle (col ^ (row & 60)) for bank spread.
// ---------------------------------------------------------------------------
__global__ __launch_bounds__(256) void proj_kernel(
    const float* __restrict__ x,
    const float* __restrict__ Wq, const float* __restrict__ bq,
    const float* __restrict__ Wk, const float* __restrict__ bk,
    const float* __restrict__ Wv, const float* __restrict__ bv)
{
    const float* W;
    const float* bias;
    float* out;
    if (blockIdx.y == 0)      { W = Wq; bias = bq; out = g_q; }
    else if (blockIdx.y == 1) { W = Wk; bias = bk; out = g_k; }
    else                      { W = Wv; bias = bv; out = g_v; }

    __shared__ float sX[64 * 64];
    __shared__ float sW[64 * 64];

    const int tid = threadIdx.x;
    const int tx = tid & 15;      // col group
    const int ty = tid >> 4;      // row group
    const int row0 = blockIdx.x * 64;

    float acc[4][4];
    #pragma unroll
    for (int i = 0; i < 4; i++)
        #pragma unroll
        for (int j = 0; j < 4; j++) acc[i][j] = 0.0f;

    const int sxa = (4 * ty) & 60;   // swizzle for my 4 X rows (same for all 4)
    const int cswz = 4 * tx;         // col-group base used in b-load swizzle

    for (int k0 = 0; k0 < En; k0 += 64) {
        #pragma unroll
        for (int t = 0; t < 4; t++) {
            int idx = tid + 256 * t;
            int r  = idx >> 4;       // 0..63
            int c4 = idx & 15;       // 0..15
            int sw = r & 60;
            float4 xv = *reinterpret_cast<const float4*>(
                &x[(size_t)(row0 + r) * En + k0 + c4 * 4]);
            *reinterpret_cast<float4*>(&sX[r * 64 + ((c4 * 4) ^ sw)]) = xv;
            float4 wv = *reinterpret_cast<const float4*>(
                &W[(size_t)(k0 + r) * Hn + c4 * 4]);
            *reinterpret_cast<float4*>(&sW[r * 64 + ((c4 * 4) ^ sw)]) = wv;
        }
        __syncthreads();

        #pragma unroll 4
        for (int kk = 0; kk < 64; kk += 4) {
            float4 a[4];
            #pragma unroll
            for (int i = 0; i < 4; i++)
                a[i] = *reinterpret_cast<const float4*>(
                    &sX[(4 * ty + i) * 64 + (kk ^ sxa)]);
            float4 bv4[4];
            #pragma unroll
            for (int u = 0; u < 4; u++)
                bv4[u] = *reinterpret_cast<const float4*>(
                    &sW[(kk + u) * 64 + (cswz ^ ((kk + u) & 60))]);
            #pragma unroll
            for (int i = 0; i < 4; i++) {
                #pragma unroll
                for (int j = 0; j < 4; j++) {
                    float bj0 = ((const float*)&bv4[0])[j];
                    float bj1 = ((const float*)&bv4[1])[j];
                    float bj2 = ((const float*)&bv4[2])[j];
                    float bj3 = ((const float*)&bv4[3])[j];
                    acc[i][j] = fmaf(a[i].x, bj0, acc[i][j]);
                    acc[i][j] = fmaf(a[i].y, bj1, acc[i][j]);
                    acc[i][j] = fmaf(a[i].z, bj2, acc[i][j]);
                    acc[i][j] = fmaf(a[i].w, bj3, acc[i][j]);
                }
            }
        }
        __syncthreads();
    }

    float4 bb = *reinterpret_cast<const float4*>(&bias[4 * tx]);
    #pragma unroll
    for (int i = 0; i < 4; i++) {
        int r = row0 + 4 * ty + i;
        float4 o4;
        o4.x = acc[i][0] + bb.x;
        o4.y = acc[i][1] + bb.y;
        o4.z = acc[i][2] + bb.z;
        o4.w = acc[i][3] + bb.w;
        *reinterpret_cast<float4*>(&out[(size_t)r * Hn + 4 * tx]) = o4;
    }
}

// ---------------------------------------------------------------------------
// Flash attention (causal + pad mask), fp32. BM=32, BN=64.
// grid: (64, 8), heavy q-tiles scheduled first (reversed blockIdx.x).
// Thread tile 2x4 contiguous: rows 2*ty..+1, cols 4*tx..+3.
// All smem in dynamic smem; XOR swizzle for bank spread; LDS.128 everywhere.
// ---------------------------------------------------------------------------
#define SQ_OFF 0
#define SK_OFF (BM * 64)
#define SV_OFF (SK_OFF + BN * 64)
#define SP_OFF (SV_OFF + BN * 64)
#define SM_OFF (SP_OFF + BM * 64)
#define ATTN_SMEM_FLOATS (SM_OFF + BN)

__global__ __launch_bounds__(256) void attn_kernel(
    const int* __restrict__ mask, float* __restrict__ out)
{
    extern __shared__ float smem[];

    const int b   = blockIdx.y;
    const int qt  = (gridDim.x - 1) - blockIdx.x;   // heavy tiles first
    const int tid = threadIdx.x;
    const int tx  = tid & 15;
    const int ty  = tid >> 4;
    const int qbase = qt * BM;

    const float* qp = g_q + (size_t)b * Sn * Hn;
    const float* kp = g_k + (size_t)b * Sn * Hn;
    const float* vp = g_v + (size_t)b * Sn * Hn;

    // Load Q tile (pre-scaled by 1/sqrt(H)=0.125), swizzled
    #pragma unroll
    for (int t = 0; t < 2; t++) {
        int idx = tid + 256 * t;
        int r  = idx >> 4;     // 0..31
        int c4 = idx & 15;
        float4 v = *reinterpret_cast<const float4*>(
            &qp[(size_t)(qbase + r) * Hn + c4 * 4]);
        v.x *= 0.125f; v.y *= 0.125f; v.z *= 0.125f; v.w *= 0.125f;
        *reinterpret_cast<float4*>(
            &smem[SQ_OFF + r * 64 + ((c4 * 4) ^ (r & 60))]) = v;
    }

    float m[2], l[2], o[2][4];
    #pragma unroll
    for (int i = 0; i < 2; i++) {
        m[i] = -1e30f;
        l[i] = 0.0f;
        #pragma unroll
        for (int j = 0; j < 4; j++) o[i][j] = 0.0f;
    }

    const int rswzQ = (2 * ty) & 60;   // same for both of my rows
    const int cbase = 4 * tx;          // my 4 cols (also the swizzle key)
    const int jt_max = (qbase + BM - 1) >> 6;

    for (int jt = 0; jt <= jt_max; jt++) {
        const int kbase = jt * BN;

        // Load K, V tiles (swizzled) + pad-mask as float addend
        #pragma unroll
        for (int t = 0; t < 4; t++) {
            int idx = tid + 256 * t;
            int r  = idx >> 4;   // 0..63
            int c4 = idx & 15;
            int sw = r & 60;
            float4 kv = *reinterpret_cast<const float4*>(
                &kp[(size_t)(kbase + r) * Hn + c4 * 4]);
            *reinterpret_cast<float4*>(
                &smem[SK_OFF + r * 64 + ((c4 * 4) ^ sw)]) = kv;
            float4 vv = *reinterpret_cast<const float4*>(
                &vp[(size_t)(kbase + r) * Hn + c4 * 4]);
            *reinterpret_cast<float4*>(
                &smem[SV_OFF + r * 64 + ((c4 * 4) ^ sw)]) = vv;
        }
        if (tid < BN)
            smem[SM_OFF + tid] = (mask[b * Sn + kbase + tid] != 0) ? 0.0f : -1e30f;
        __syncthreads();

        // S = Q * K^T (reduction over H, both row-major in H)
        float s[2][4];
        #pragma unroll
        for (int i = 0; i < 2; i++)
            #pragma unroll
            for (int j = 0; j < 4; j++) s[i][j] = 0.0f;

        #pragma unroll 4
        for (int kk = 0; kk < Hn; kk += 4) {
            float4 q0 = *reinterpret_cast<const float4*>(
                &smem[SQ_OFF + (2 * ty) * 64 + (kk ^ rswzQ)]);
            float4 q1 = *reinterpret_cast<const float4*>(
                &smem[SQ_OFF + (2 * ty + 1) * 64 + (kk ^ rswzQ)]);
            #pragma unroll
            for (int j = 0; j < 4; j++) {
                float4 kv4 = *reinterpret_cast<const float4*>(
                    &smem[SK_OFF + (cbase + j) * 64 + (kk ^ ((cbase + j) & 60))]);
                s[0][j] = fmaf(q0.x, kv4.x, s[0][j]);
                s[0][j] = fmaf(q0.y, kv4.y, s[0][j]);
                s[0][j] = fmaf(q0.z, kv4.z, s[0][j]);
                s[0][j] = fmaf(q0.w, kv4.w, s[0][j]);
                s[1][j] = fmaf(q1.x, kv4.x, s[1][j]);
                s[1][j] = fmaf(q1.y, kv4.y, s[1][j]);
                s[1][j] = fmaf(q1.z, kv4.z, s[1][j]);
                s[1][j] = fmaf(q1.w, kv4.w, s[1][j]);
            }
        }

        // Mask + online softmax update, write P (swizzled) to smem
        const bool need_causal = (kbase + BN - 1) > qbase;
        float padd[4];
        #pragma unroll
        for (int j = 0; j < 4; j++) padd[j] = smem[SM_OFF + cbase + j];

        #pragma unroll
        for (int i = 0; i < 2; i++) {
            const int qrow = qbase + 2 * ty + i;
            float sm4[4];
            #pragma unroll
            for (int j = 0; j < 4; j++) {
                float v = s[i][j] + padd[j];
                if (need_causal && (kbase + cbase + j > qrow)) v = -1e30f;
                sm4[j] = v;
            }
            float tmax = fmaxf(fmaxf(sm4[0], sm4[1]), fmaxf(sm4[2], sm4[3]));
            #pragma unroll
            for (int off = 8; off > 0; off >>= 1)
                tmax = fmaxf(tmax, __shfl_xor_sync(0xffffffffu, tmax, off));

            const float mnew = fmaxf(m[i], tmax);
            const float alpha = __expf(m[i] - mnew);

            float4 p4;
            p4.x = __expf(sm4[0] - mnew);
            p4.y = __expf(sm4[1] - mnew);
            p4.z = __expf(sm4[2] - mnew);
            p4.w = __expf(sm4[3] - mnew);
            float ps = (p4.x + p4.y) + (p4.z + p4.w);

            const int prow = 2 * ty + i;
            *reinterpret_cast<float4*>(
                &smem[SP_OFF + prow * 64 + (cbase ^ (prow & 60))]) = p4;

            #pragma unroll
            for (int off = 8; off > 0; off >>= 1)
                ps += __shfl_xor_sync(0xffffffffu, ps, off);

            l[i] = l[i] * alpha + ps;
            m[i] = mnew;
            #pragma unroll
            for (int j = 0; j < 4; j++) o[i][j] *= alpha;
        }
        __syncthreads();   // P fully visible

        // O += P * V (reduction over kv; P and V row-major in their k dims)
        #pragma unroll 4
        for (int kv = 0; kv < BN; kv += 4) {
            float4 p0 = *reinterpret_cast<const float4*>(
                &smem[SP_OFF + (2 * ty) * 64 + (kv ^ rswzQ)]);
            float4 p1 = *reinterpret_cast<const float4*>(
                &smem[SP_OFF + (2 * ty + 1) * 64 + (kv ^ rswzQ)]);
            const int vsw = cbase ^ (kv & 60);
            float4 v0 = *reinterpret_cast<const float4*>(
                &smem[SV_OFF + (kv + 0) * 64 + vsw]);
            float4 v1 = *reinterpret_cast<const float4*>(
                &smem[SV_OFF + (kv + 1) * 64 + vsw]);
            float4 v2 = *reinterpret_cast<const float4*>(
                &smem[SV_OFF + (kv + 2) * 64 + vsw]);
            float4 v3 = *reinterpret_cast<const float4*>(
                &smem[SV_OFF + (kv + 3) * 64 + vsw]);
            const float* vp0 = (const float*)&v0;
            const float* vp1 = (const float*)&v1;
            const float* vp2 = (const float*)&v2;
            const float* vp3 = (const float*)&v3;
            #pragma unroll
            for (int j = 0; j < 4; j++) {
                o[0][j] = fmaf(p0.x, vp0[j], o[0][j]);
                o[0][j] = fmaf(p0.y, vp1[j], o[0][j]);
                o[0][j] = fmaf(p0.z, vp2[j], o[0][j]);
                o[0][j] = fmaf(p0.w, vp3[j], o[0][j]);
                o[1][j] = fmaf(p1.x, vp0[j], o[1][j]);
                o[1][j] = fmaf(p1.y, vp1[j], o[1][j]);
                o[1][j] = fmaf(p1.z, vp2[j], o[1][j]);
                o[1][j] = fmaf(p1.w, vp3[j], o[1][j]);
            }
        }
        __syncthreads();   // done with sK/sV/sP before next tile overwrites
    }

    // Normalize and write
    #pragma unroll
    for (int i = 0; i < 2; i++) {
        const int r = qbase + 2 * ty + i;
        const float inv = 1.0f / l[i];
        float4 o4;
        o4.x = o[i][0] * inv;
        o4.y = o[i][1] * inv;
        o4.z = o[i][2] * inv;
        o4.w = o[i][3] * inv;
        *reinterpret_cast<float4*>(&out[((size_t)b * Sn + r) * Hn + 4 * tx]) = o4;
    }
}

static const int ATTN_SMEM_BYTES = ATTN_SMEM_FLOATS * (int)sizeof(float);

extern "C" void kernel_launch(void* const* d_in, const int* in_sizes, int n_in,
                              void* d_out, int out_size)
{
    const float* x    = (const float*)d_in[0];
    const int*   mask = (const int*)d_in[1];
    const float* Wq   = (const float*)d_in[2];
    const float* bq   = (const float*)d_in[3];
    const float* Wk   = (const float*)d_in[4];
    const float* bk   = (const float*)d_in[5];
    const float* Wv   = (const float*)d_in[6];
    const float* bv   = (const float*)d_in[7];
    float* out = (float*)d_out;

    static bool attr_set = false;
    if (!attr_set) {
        cudaFuncSetAttribute(attn_kernel,
                             cudaFuncAttributeMaxDynamicSharedMemorySize,
                             ATTN_SMEM_BYTES);
        attr_set = true;
    }

    dim3 gproj(Bn * Sn / 64, 3);
    proj_kernel<<<gproj, 256>>>(x, Wq, bq, Wk, bk, Wv, bv);

    dim3 gattn(Sn / BM, Bn);
    attn_kernel<<<gattn, 256, ATTN_SMEM_BYTES>>>(mask, out);
}

// round 5
// speedup vs baseline: 1.6810x; 1.3320x over previous
#include <cuda_runtime.h>
#include <math.h>
#include <cstdint>

#define Bn 8
#define Sn 2048
#define En 1024
#define Hn 64

// Scratch for q,k,v: [B,S,H] fp32 (4 MB each)
__device__ float g_q[Bn * Sn * Hn];
__device__ float g_k[Bn * Sn * Hn];
__device__ float g_v[Bn * Sn * Hn];

// m16n8k8 tf32 mma: D += A*B, fp32 accumulate. a/b hold tf32 bit patterns.
__device__ __forceinline__ void mma_tf32(float d[4], const uint32_t a[4],
                                         uint32_t b0, uint32_t b1)
{
    asm volatile(
        "mma.sync.aligned.m16n8k8.row.col.f32.tf32.tf32.f32 "
        "{%0,%1,%2,%3}, {%4,%5,%6,%7}, {%8,%9}, {%0,%1,%2,%3};"
        : "+f"(d[0]), "+f"(d[1]), "+f"(d[2]), "+f"(d[3])
        : "r"(a[0]), "r"(a[1]), "r"(a[2]), "r"(a[3]), "r"(b0), "r"(b1));
}

// 3xTF32 split: hi = round-to-nearest tf32, lo = residual (fp32 bits; mma
// truncates it to tf32, adding only ~2^-23 relative error).
__device__ __forceinline__ void split_tf32(float x, uint32_t& hi, uint32_t& lo)
{
    uint32_t h;
    asm("cvt.rna.tf32.f32 %0, %1;" : "=r"(h) : "f"(x));
    hi = h;
    lo = __float_as_uint(x - __uint_as_float(h));
}

// One compensated MMA: d += a*b using hi/lo splits (3 HMMAs)
__device__ __forceinline__ void mma3(float d[4],
                                     const uint32_t ah[4], const uint32_t al[4],
                                     uint32_t bh0, uint32_t bl0,
                                     uint32_t bh1, uint32_t bl1)
{
    mma_tf32(d, ah, bh0, bh1);
    mma_tf32(d, ah, bl0, bl1);
    mma_tf32(d, al, bh0, bh1);
}

// ---------------------------------------------------------------------------
// Projection: [16384,1024] x [1024,192] (+bias) -> g_q|g_k|g_v
// CTA: 64 rows x 192 cols, 8 warps: wm=warp&3 (16-row group), wn=warp>>2.
// ---------------------------------------------------------------------------
#define PXS 36
#define PWS 196

__global__ __launch_bounds__(256) void proj_mma_kernel(
    const float* __restrict__ x,
    const float* __restrict__ Wq, const float* __restrict__ bq,
    const float* __restrict__ Wk, const float* __restrict__ bk,
    const float* __restrict__ Wv, const float* __restrict__ bv)
{
    __shared__ float sX[64 * PXS];
    __shared__ float sW[32 * PWS];
    __shared__ float sB[192];

    const int tid  = threadIdx.x;
    const int warp = tid >> 5;
    const int lane = tid & 31;
    const int g    = lane >> 2;
    const int tg   = lane & 3;
    const int wm   = warp & 3;
    const int wn   = warp >> 2;
    const int row0 = blockIdx.x * 64;

    if (tid < 192)
        sB[tid] = (tid < 64) ? bq[tid] : (tid < 128 ? bk[tid - 64] : bv[tid - 128]);

    float acc[12][4];
    #pragma unroll
    for (int t = 0; t < 12; t++)
        #pragma unroll
        for (int i = 0; i < 4; i++) acc[t][i] = 0.0f;

    for (int k0 = 0; k0 < En; k0 += 32) {
        #pragma unroll
        for (int u = 0; u < 2; u++) {
            int idx = tid + 256 * u;
            int r = idx >> 3, c = idx & 7;
            float4 v = *reinterpret_cast<const float4*>(
                &x[(size_t)(row0 + r) * En + k0 + 4 * c]);
            *reinterpret_cast<float4*>(&sX[r * PXS + 4 * c]) = v;
        }
        #pragma unroll
        for (int u = 0; u < 6; u++) {
            int idx = tid + 256 * u;
            int r = idx / 48, c4 = idx % 48;
            int col = 4 * c4;
            const float* Wm = (col < 64) ? Wq : (col < 128 ? Wk : Wv);
            float4 v = *reinterpret_cast<const float4*>(
                &Wm[(size_t)(k0 + r) * Hn + (col & 63)]);
            *reinterpret_cast<float4*>(&sW[r * PWS + col]) = v;
        }
        __syncthreads();

        #pragma unroll
        for (int kk = 0; kk < 4; kk++) {
            uint32_t ah[4], al[4];
            const int ar0 = (16 * wm + g) * PXS + 8 * kk + tg;
            split_tf32(sX[ar0],               ah[0], al[0]);
            split_tf32(sX[ar0 + 8 * PXS],     ah[1], al[1]);
            split_tf32(sX[ar0 + 4],           ah[2], al[2]);
            split_tf32(sX[ar0 + 8 * PXS + 4], ah[3], al[3]);
            #pragma unroll
            for (int t = 0; t < 12; t++) {
                const int n = wn * 96 + 8 * t + g;
                uint32_t bh0, bl0, bh1, bl1;
                split_tf32(sW[(8 * kk + tg) * PWS + n],     bh0, bl0);
                split_tf32(sW[(8 * kk + tg + 4) * PWS + n], bh1, bl1);
                mma3(acc[t], ah, al, bh0, bl0, bh1, bl1);
            }
        }
        __syncthreads();
    }

    const int r0 = row0 + 16 * wm + g;
    #pragma unroll
    for (int t = 0; t < 12; t++) {
        const int col = wn * 96 + 8 * t + 2 * tg;
        float* dst = (col < 64) ? g_q : (col < 128 ? g_k : g_v);
        const int lcol = col & 63;
        float2 v0, v1;
        v0.x = acc[t][0] + sB[col];
        v0.y = acc[t][1] + sB[col + 1];
        v1.x = acc[t][2] + sB[col];
        v1.y = acc[t][3] + sB[col + 1];
        *reinterpret_cast<float2*>(&dst[(size_t)r0 * Hn + lcol]) = v0;
        *reinterpret_cast<float2*>(&dst[(size_t)(r0 + 8) * Hn + lcol]) = v1;
    }
}

// ---------------------------------------------------------------------------
// Flash attention via 3xTF32 mma.sync. CTA: 64 q-rows, 4 warps x 16 rows.
// ---------------------------------------------------------------------------
#define AST 68

__global__ __launch_bounds__(128) void attn_mma_kernel(
    const int* __restrict__ mask, float* __restrict__ out)
{
    extern __shared__ float sm[];
    float* sK = sm;                 // 64 x AST
    float* sV = sm + 64 * AST;      // 64 x AST
    float* sP = sm + 2 * 64 * AST;  // 64 x AST
    float* sM = sm + 3 * 64 * AST;  // 64

    const int b   = blockIdx.y;
    const int qt  = (gridDim.x - 1) - blockIdx.x;
    const int qbase = qt * 64;
    const int tid  = threadIdx.x;
    const int warp = tid >> 5;
    const int lane = tid & 31;
    const int g    = lane >> 2;
    const int tg   = lane & 3;
    const int wrow = warp * 16;

    const float* qp = g_q + ((size_t)b * Sn + qbase + wrow) * Hn;
    const float* kp = g_k + (size_t)b * Sn * Hn;
    const float* vp = g_v + (size_t)b * Sn * Hn;

    // Q fragments (pre-scaled by 0.125), persistent hi/lo splits
    uint32_t qh[8][4], ql[8][4];
    #pragma unroll
    for (int kc = 0; kc < 8; kc++) {
        split_tf32(qp[(size_t)g * Hn + 8 * kc + tg] * 0.125f,           qh[kc][0], ql[kc][0]);
        split_tf32(qp[(size_t)(g + 8) * Hn + 8 * kc + tg] * 0.125f,     qh[kc][1], ql[kc][1]);
        split_tf32(qp[(size_t)g * Hn + 8 * kc + tg + 4] * 0.125f,       qh[kc][2], ql[kc][2]);
        split_tf32(qp[(size_t)(g + 8) * Hn + 8 * kc + tg + 4] * 0.125f, qh[kc][3], ql[kc][3]);
    }

    float m0 = -1e30f, m1 = -1e30f, l0 = 0.0f, l1 = 0.0f;
    float o[8][4];
    #pragma unroll
    for (int t = 0; t < 8; t++)
        #pragma unroll
        for (int i = 0; i < 4; i++) o[t][i] = 0.0f;

    for (int jt = 0; jt <= qt; jt++) {
        const int kbase = jt * 64;

        #pragma unroll
        for (int u = 0; u < 8; u++) {
            int idx = tid + 128 * u;
            int r = idx >> 4, c4 = idx & 15;
            float4 kv = *reinterpret_cast<const float4*>(
                &kp[(size_t)(kbase + r) * Hn + 4 * c4]);
            *reinterpret_cast<float4*>(&sK[r * AST + 4 * c4]) = kv;
            float4 vv = *reinterpret_cast<const float4*>(
                &vp[(size_t)(kbase + r) * Hn + 4 * c4]);
            *reinterpret_cast<float4*>(&sV[r * AST + 4 * c4]) = vv;
        }
        if (tid < 64)
            sM[tid] = (mask[b * Sn + kbase + tid] != 0) ? 0.0f : -1e30f;
        __syncthreads();

        // S = Q * K^T (3xTF32)
        float s[8][4];
        #pragma unroll
        for (int t = 0; t < 8; t++)
            #pragma unroll
            for (int i = 0; i < 4; i++) s[t][i] = 0.0f;

        #pragma unroll
        for (int t = 0; t < 8; t++) {
            const int krow = (8 * t + g) * AST;
            #pragma unroll
            for (int kc = 0; kc < 8; kc++) {
                uint32_t bh0, bl0, bh1, bl1;
                split_tf32(sK[krow + 8 * kc + tg],     bh0, bl0);
                split_tf32(sK[krow + 8 * kc + tg + 4], bh1, bl1);
                mma3(s[t], qh[kc], ql[kc], bh0, bl0, bh1, bl1);
            }
        }

        // Mask + online softmax
        const bool diag = (jt == qt);
        const int lrow0 = wrow + g;
        float rmax0 = -1e30f, rmax1 = -1e30f;
        #pragma unroll
        for (int t = 0; t < 8; t++) {
            const int c = 8 * t + 2 * tg;
            const float pa0 = sM[c], pa1 = sM[c + 1];
            s[t][0] += pa0; s[t][1] += pa1;
            s[t][2] += pa0; s[t][3] += pa1;
            if (diag) {
                if (c > lrow0)         s[t][0] = -1e30f;
                if (c + 1 > lrow0)     s[t][1] = -1e30f;
                if (c > lrow0 + 8)     s[t][2] = -1e30f;
                if (c + 1 > lrow0 + 8) s[t][3] = -1e30f;
            }
            rmax0 = fmaxf(rmax0, fmaxf(s[t][0], s[t][1]));
            rmax1 = fmaxf(rmax1, fmaxf(s[t][2], s[t][3]));
        }
        rmax0 = fmaxf(rmax0, __shfl_xor_sync(0xffffffffu, rmax0, 1));
        rmax0 = fmaxf(rmax0, __shfl_xor_sync(0xffffffffu, rmax0, 2));
        rmax1 = fmaxf(rmax1, __shfl_xor_sync(0xffffffffu, rmax1, 1));
        rmax1 = fmaxf(rmax1, __shfl_xor_sync(0xffffffffu, rmax1, 2));

        const float mn0 = fmaxf(m0, rmax0);
        const float mn1 = fmaxf(m1, rmax1);
        const float al0 = __expf(m0 - mn0);
        const float al1 = __expf(m1 - mn1);

        float ps0 = 0.0f, ps1 = 0.0f;
        #pragma unroll
        for (int t = 0; t < 8; t++) {
            float p00 = __expf(s[t][0] - mn0);
            float p01 = __expf(s[t][1] - mn0);
            float p10 = __expf(s[t][2] - mn1);
            float p11 = __expf(s[t][3] - mn1);
            ps0 += p00 + p01;
            ps1 += p10 + p11;
            float2 w0; w0.x = p00; w0.y = p01;
            float2 w1; w1.x = p10; w1.y = p11;
            *reinterpret_cast<float2*>(&sP[(wrow + g) * AST + 8 * t + 2 * tg]) = w0;
            *reinterpret_cast<float2*>(&sP[(wrow + g + 8) * AST + 8 * t + 2 * tg]) = w1;
        }
        ps0 += __shfl_xor_sync(0xffffffffu, ps0, 1);
        ps0 += __shfl_xor_sync(0xffffffffu, ps0, 2);
        ps1 += __shfl_xor_sync(0xffffffffu, ps1, 1);
        ps1 += __shfl_xor_sync(0xffffffffu, ps1, 2);

        l0 = l0 * al0 + ps0;
        l1 = l1 * al1 + ps1;
        m0 = mn0;
        m1 = mn1;
        #pragma unroll
        for (int t = 0; t < 8; t++) {
            o[t][0] *= al0; o[t][1] *= al0;
            o[t][2] *= al1; o[t][3] *= al1;
        }
        __syncwarp();

        // O += P * V (3xTF32)
        #pragma unroll
        for (int kc = 0; kc < 8; kc++) {
            uint32_t ah[4], al_[4];
            const int pr0 = (wrow + g) * AST + 8 * kc + tg;
            split_tf32(sP[pr0],               ah[0], al_[0]);
            split_tf32(sP[pr0 + 8 * AST],     ah[1], al_[1]);
            split_tf32(sP[pr0 + 4],           ah[2], al_[2]);
            split_tf32(sP[pr0 + 8 * AST + 4], ah[3], al_[3]);
            #pragma unroll
            for (int t = 0; t < 8; t++) {
                uint32_t bh0, bl0, bh1, bl1;
                split_tf32(sV[(8 * kc + tg) * AST + 8 * t + g],     bh0, bl0);
                split_tf32(sV[(8 * kc + tg + 4) * AST + 8 * t + g], bh1, bl1);
                mma3(o[t], ah, al_, bh0, bl0, bh1, bl1);
            }
        }
        __syncthreads();
    }

    const float inv0 = 1.0f / l0;
    const float inv1 = 1.0f / l1;
    const size_t r0 = (size_t)b * Sn + qbase + wrow + g;
    #pragma unroll
    for (int t = 0; t < 8; t++) {
        const int col = 8 * t + 2 * tg;
        float2 w0, w1;
        w0.x = o[t][0] * inv0; w0.y = o[t][1] * inv0;
        w1.x = o[t][2] * inv1; w1.y = o[t][3] * inv1;
        *reinterpret_cast<float2*>(&out[r0 * Hn + col]) = w0;
        *reinterpret_cast<float2*>(&out[(r0 + 8) * Hn + col]) = w1;
    }
}

static const int ATTN_SMEM_BYTES = (3 * 64 * AST + 64) * (int)sizeof(float);

extern "C" void kernel_launch(void* const* d_in, const int* in_sizes, int n_in,
                              void* d_out, int out_size)
{
    const float* x    = (const float*)d_in[0];
    const int*   mask = (const int*)d_in[1];
    const float* Wq   = (const float*)d_in[2];
    const float* bq   = (const float*)d_in[3];
    const float* Wk   = (const float*)d_in[4];
    const float* bk   = (const float*)d_in[5];
    const float* Wv   = (const float*)d_in[6];
    const float* bv   = (const float*)d_in[7];
    float* out = (float*)d_out;

    cudaFuncSetAttribute(attn_mma_kernel,
                         cudaFuncAttributeMaxDynamicSharedMemorySize,
                         ATTN_SMEM_BYTES);

    proj_mma_kernel<<<Bn * Sn / 64, 256>>>(x, Wq, bq, Wk, bk, Wv, bv);

    dim3 gattn(Sn / 64, Bn);
    attn_mma_kernel<<<gattn, 128, ATTN_SMEM_BYTES>>>(mask, out);
}

// round 6
// speedup vs baseline: 2.3642x; 1.4065x over previous
#include <cuda_runtime.h>
#include <math.h>
#include <cstdint>

#define Bn 8
#define Sn 2048
#define En 1024
#define Hn 64

// Scratch: q,k,v [B,S,H]; split-KV partials (unnormalized O + m/l per half)
__device__ float g_q[Bn * Sn * Hn];
__device__ float g_k[Bn * Sn * Hn];
__device__ float g_v[Bn * Sn * Hn];
__device__ float g_op0[Bn * Sn * Hn];
__device__ float g_op1[Bn * Sn * Hn];
__device__ float g_ml0[Bn * Sn * 2];
__device__ float g_ml1[Bn * Sn * 2];

// m16n8k8 tf32 mma: D += A*B, fp32 accumulate.
__device__ __forceinline__ void mma_tf32(float d[4], const uint32_t a[4],
                                         uint32_t b0, uint32_t b1)
{
    asm volatile(
        "mma.sync.aligned.m16n8k8.row.col.f32.tf32.tf32.f32 "
        "{%0,%1,%2,%3}, {%4,%5,%6,%7}, {%8,%9}, {%0,%1,%2,%3};"
        : "+f"(d[0]), "+f"(d[1]), "+f"(d[2]), "+f"(d[3])
        : "r"(a[0]), "r"(a[1]), "r"(a[2]), "r"(a[3]), "r"(b0), "r"(b1));
}

__device__ __forceinline__ uint32_t f2u(float f) { return __float_as_uint(f); }

__device__ __forceinline__ void split_tf32(float x, uint32_t& hi, uint32_t& lo)
{
    uint32_t h;
    asm("cvt.rna.tf32.f32 %0, %1;" : "=r"(h) : "f"(x));
    hi = h;
    lo = __float_as_uint(x - __uint_as_float(h));
}
// split a float into hi/lo stored as floats (bit patterns)
__device__ __forceinline__ void split_f(float x, float& hf, float& lf)
{
    uint32_t h, l;
    split_tf32(x, h, l);
    hf = __uint_as_float(h);
    lf = __uint_as_float(l);
}

__device__ __forceinline__ void mma3(float d[4],
                                     const uint32_t ah[4], const uint32_t al[4],
                                     uint32_t bh0, uint32_t bl0,
                                     uint32_t bh1, uint32_t bl1)
{
    mma_tf32(d, ah, bh0, bh1);
    mma_tf32(d, ah, bl0, bl1);
    mma_tf32(d, al, bh0, bh1);
}

// ---------------------------------------------------------------------------
// Projection: [16384,1024] x [1024,192] (+bias) -> g_q|g_k|g_v
// Pre-split hi/lo tiles in dynamic smem. Strides: X 36 (4g+tg), W 200 (8tg+g).
// ---------------------------------------------------------------------------
#define PXS 36
#define PWS 200
// float offsets in dynamic smem
#define PJ_XH 0
#define PJ_XL (PJ_XH + 64 * PXS)
#define PJ_WH (PJ_XL + 64 * PXS)
#define PJ_WL (PJ_WH + 32 * PWS)
#define PJ_B  (PJ_WL + 32 * PWS)
#define PJ_TOT (PJ_B + 192)

__global__ __launch_bounds__(256) void proj_mma_kernel(
    const float* __restrict__ x,
    const float* __restrict__ Wq, const float* __restrict__ bq,
    const float* __restrict__ Wk, const float* __restrict__ bk,
    const float* __restrict__ Wv, const float* __restrict__ bv)
{
    extern __shared__ float sm[];
    float* sXh = sm + PJ_XH;
    float* sXl = sm + PJ_XL;
    float* sWh = sm + PJ_WH;
    float* sWl = sm + PJ_WL;
    float* sB  = sm + PJ_B;

    const int tid  = threadIdx.x;
    const int warp = tid >> 5;
    const int lane = tid & 31;
    const int g    = lane >> 2;
    const int tg   = lane & 3;
    const int wm   = warp & 3;
    const int wn   = warp >> 2;
    const int row0 = blockIdx.x * 64;

    if (tid < 192)
        sB[tid] = (tid < 64) ? bq[tid] : (tid < 128 ? bk[tid - 64] : bv[tid - 128]);

    float acc[12][4];
    #pragma unroll
    for (int t = 0; t < 12; t++)
        #pragma unroll
        for (int i = 0; i < 4; i++) acc[t][i] = 0.0f;

    for (int k0 = 0; k0 < En; k0 += 32) {
        #pragma unroll
        for (int u = 0; u < 2; u++) {
            int idx = tid + 256 * u;
            int r = idx >> 3, c = idx & 7;
            float4 v = *reinterpret_cast<const float4*>(
                &x[(size_t)(row0 + r) * En + k0 + 4 * c]);
            float4 h4, l4;
            split_f(v.x, h4.x, l4.x); split_f(v.y, h4.y, l4.y);
            split_f(v.z, h4.z, l4.z); split_f(v.w, h4.w, l4.w);
            *reinterpret_cast<float4*>(&sXh[r * PXS + 4 * c]) = h4;
            *reinterpret_cast<float4*>(&sXl[r * PXS + 4 * c]) = l4;
        }
        #pragma unroll
        for (int u = 0; u < 6; u++) {
            int idx = tid + 256 * u;
            int r = idx / 48, c4 = idx % 48;
            int col = 4 * c4;
            const float* Wm = (col < 64) ? Wq : (col < 128 ? Wk : Wv);
            float4 v = *reinterpret_cast<const float4*>(
                &Wm[(size_t)(k0 + r) * Hn + (col & 63)]);
            float4 h4, l4;
            split_f(v.x, h4.x, l4.x); split_f(v.y, h4.y, l4.y);
            split_f(v.z, h4.z, l4.z); split_f(v.w, h4.w, l4.w);
            *reinterpret_cast<float4*>(&sWh[r * PWS + col]) = h4;
            *reinterpret_cast<float4*>(&sWl[r * PWS + col]) = l4;
        }
        __syncthreads();

        #pragma unroll
        for (int kk = 0; kk < 4; kk++) {
            uint32_t ah[4], al[4];
            const int ar0 = (16 * wm + g) * PXS + 8 * kk + tg;
            ah[0] = f2u(sXh[ar0]);               al[0] = f2u(sXl[ar0]);
            ah[1] = f2u(sXh[ar0 + 8 * PXS]);     al[1] = f2u(sXl[ar0 + 8 * PXS]);
            ah[2] = f2u(sXh[ar0 + 4]);           al[2] = f2u(sXl[ar0 + 4]);
            ah[3] = f2u(sXh[ar0 + 8 * PXS + 4]); al[3] = f2u(sXl[ar0 + 8 * PXS + 4]);
            #pragma unroll
            for (int t = 0; t < 12; t++) {
                const int n = wn * 96 + 8 * t + g;
                const int b0i = (8 * kk + tg) * PWS + n;
                const int b1i = (8 * kk + tg + 4) * PWS + n;
                mma3(acc[t], ah, al,
                     f2u(sWh[b0i]), f2u(sWl[b0i]),
                     f2u(sWh[b1i]), f2u(sWl[b1i]));
            }
        }
        __syncthreads();
    }

    const int r0 = row0 + 16 * wm + g;
    #pragma unroll
    for (int t = 0; t < 12; t++) {
        const int col = wn * 96 + 8 * t + 2 * tg;
        float* dst = (col < 64) ? g_q : (col < 128 ? g_k : g_v);
        const int lcol = col & 63;
        float2 v0, v1;
        v0.x = acc[t][0] + sB[col];
        v0.y = acc[t][1] + sB[col + 1];
        v1.x = acc[t][2] + sB[col];
        v1.y = acc[t][3] + sB[col + 1];
        *reinterpret_cast<float2*>(&dst[(size_t)r0 * Hn + lcol]) = v0;
        *reinterpret_cast<float2*>(&dst[(size_t)(r0 + 8) * Hn + lcol]) = v1;
    }
}

// ---------------------------------------------------------------------------
// Flash attention, split-KV (2 halves per q-tile), pre-split hi/lo smem.
// CTA: 64 q-rows, 4 warps x 16 rows. grid (32, 8, 2).
// Strides: K/P 68 (frag bank 4g+tg), V 72 (frag bank 8tg+g).
// ---------------------------------------------------------------------------
#define ASK 68
#define ASV 72
// float offsets
#define AT_KH 0
#define AT_KL (AT_KH + 64 * ASK)
#define AT_VH (AT_KL + 64 * ASK)
#define AT_VL (AT_VH + 64 * ASV)
#define AT_PH (AT_VL + 64 * ASV)
#define AT_PL (AT_PH + 64 * ASK)
#define AT_M  (AT_PL + 64 * ASK)
#define AT_TOT (AT_M + 64)

__global__ __launch_bounds__(128) void attn_mma_kernel(
    const int* __restrict__ mask)
{
    extern __shared__ float sm[];
    float* sKh = sm + AT_KH;
    float* sKl = sm + AT_KL;
    float* sVh = sm + AT_VH;
    float* sVl = sm + AT_VL;
    float* sPh = sm + AT_PH;
    float* sPl = sm + AT_PL;
    float* sM  = sm + AT_M;

    const int b    = blockIdx.y;
    const int qt   = (gridDim.x - 1) - blockIdx.x;   // heavy tiles first
    const int half = blockIdx.z;
    const int qbase = qt * 64;
    const int tid  = threadIdx.x;
    const int warp = tid >> 5;
    const int lane = tid & 31;
    const int g    = lane >> 2;
    const int tg   = lane & 3;
    const int wrow = warp * 16;

    const int nt  = qt + 1;
    const int nt0 = (nt + 1) >> 1;
    const int jt_begin = half ? nt0 : 0;
    const int jt_end   = half ? nt : nt0;

    const float* qp = g_q + ((size_t)b * Sn + qbase + wrow) * Hn;
    const float* kp = g_k + (size_t)b * Sn * Hn;
    const float* vp = g_v + (size_t)b * Sn * Hn;

    // Q fragments (pre-scaled by 0.125), persistent hi/lo splits
    uint32_t qh[8][4], ql[8][4];
    #pragma unroll
    for (int kc = 0; kc < 8; kc++) {
        split_tf32(qp[(size_t)g * Hn + 8 * kc + tg] * 0.125f,           qh[kc][0], ql[kc][0]);
        split_tf32(qp[(size_t)(g + 8) * Hn + 8 * kc + tg] * 0.125f,     qh[kc][1], ql[kc][1]);
        split_tf32(qp[(size_t)g * Hn + 8 * kc + tg + 4] * 0.125f,       qh[kc][2], ql[kc][2]);
        split_tf32(qp[(size_t)(g + 8) * Hn + 8 * kc + tg + 4] * 0.125f, qh[kc][3], ql[kc][3]);
    }

    float m0 = -1e30f, m1 = -1e30f, l0 = 0.0f, l1 = 0.0f;
    float o[8][4];
    #pragma unroll
    for (int t = 0; t < 8; t++)
        #pragma unroll
        for (int i = 0; i < 4; i++) o[t][i] = 0.0f;

    for (int jt = jt_begin; jt < jt_end; jt++) {
        const int kbase = jt * 64;

        // Load + pre-split K, V tiles; mask addend
        #pragma unroll
        for (int u = 0; u < 8; u++) {
            int idx = tid + 128 * u;
            int r = idx >> 4, c4 = idx & 15;
            float4 kv = *reinterpret_cast<const float4*>(
                &kp[(size_t)(kbase + r) * Hn + 4 * c4]);
            float4 h4, l4;
            split_f(kv.x, h4.x, l4.x); split_f(kv.y, h4.y, l4.y);
            split_f(kv.z, h4.z, l4.z); split_f(kv.w, h4.w, l4.w);
            *reinterpret_cast<float4*>(&sKh[r * ASK + 4 * c4]) = h4;
            *reinterpret_cast<float4*>(&sKl[r * ASK + 4 * c4]) = l4;
            float4 vv = *reinterpret_cast<const float4*>(
                &vp[(size_t)(kbase + r) * Hn + 4 * c4]);
            split_f(vv.x, h4.x, l4.x); split_f(vv.y, h4.y, l4.y);
            split_f(vv.z, h4.z, l4.z); split_f(vv.w, h4.w, l4.w);
            *reinterpret_cast<float4*>(&sVh[r * ASV + 4 * c4]) = h4;
            *reinterpret_cast<float4*>(&sVl[r * ASV + 4 * c4]) = l4;
        }
        if (tid < 64)
            sM[tid] = (mask[b * Sn + kbase + tid] != 0) ? 0.0f : -1e30f;
        __syncthreads();

        // S = Q * K^T (3xTF32, pure LDS feed)
        float s[8][4];
        #pragma unroll
        for (int t = 0; t < 8; t++)
            #pragma unroll
            for (int i = 0; i < 4; i++) s[t][i] = 0.0f;

        #pragma unroll
        for (int t = 0; t < 8; t++) {
            const int krow = (8 * t + g) * ASK;
            #pragma unroll
            for (int kc = 0; kc < 8; kc++) {
                const int i0 = krow + 8 * kc + tg;
                const int i1 = krow + 8 * kc + tg + 4;
                mma3(s[t], qh[kc], ql[kc],
                     f2u(sKh[i0]), f2u(sKl[i0]),
                     f2u(sKh[i1]), f2u(sKl[i1]));
            }
        }

        // Mask + online softmax
        const bool diag = (jt == qt);
        const int lrow0 = wrow + g;
        float rmax0 = -1e30f, rmax1 = -1e30f;
        #pragma unroll
        for (int t = 0; t < 8; t++) {
            const int c = 8 * t + 2 * tg;
            const float pa0 = sM[c], pa1 = sM[c + 1];
            s[t][0] += pa0; s[t][1] += pa1;
            s[t][2] += pa0; s[t][3] += pa1;
            if (diag) {
                if (c > lrow0)         s[t][0] = -1e30f;
                if (c + 1 > lrow0)     s[t][1] = -1e30f;
                if (c > lrow0 + 8)     s[t][2] = -1e30f;
                if (c + 1 > lrow0 + 8) s[t][3] = -1e30f;
            }
            rmax0 = fmaxf(rmax0, fmaxf(s[t][0], s[t][1]));
            rmax1 = fmaxf(rmax1, fmaxf(s[t][2], s[t][3]));
        }
        rmax0 = fmaxf(rmax0, __shfl_xor_sync(0xffffffffu, rmax0, 1));
        rmax0 = fmaxf(rmax0, __shfl_xor_sync(0xffffffffu, rmax0, 2));
        rmax1 = fmaxf(rmax1, __shfl_xor_sync(0xffffffffu, rmax1, 1));
        rmax1 = fmaxf(rmax1, __shfl_xor_sync(0xffffffffu, rmax1, 2));

        const float mn0 = fmaxf(m0, rmax0);
        const float mn1 = fmaxf(m1, rmax1);
        const float al0 = __expf(m0 - mn0);
        const float al1 = __expf(m1 - mn1);

        float ps0 = 0.0f, ps1 = 0.0f;
        #pragma unroll
        for (int t = 0; t < 8; t++) {
            float p00 = __expf(s[t][0] - mn0);
            float p01 = __expf(s[t][1] - mn0);
            float p10 = __expf(s[t][2] - mn1);
            float p11 = __expf(s[t][3] - mn1);
            ps0 += p00 + p01;
            ps1 += p10 + p11;
            float2 h2, l2;
            split_f(p00, h2.x, l2.x); split_f(p01, h2.y, l2.y);
            *reinterpret_cast<float2*>(&sPh[(wrow + g) * ASK + 8 * t + 2 * tg]) = h2;
            *reinterpret_cast<float2*>(&sPl[(wrow + g) * ASK + 8 * t + 2 * tg]) = l2;
            split_f(p10, h2.x, l2.x); split_f(p11, h2.y, l2.y);
            *reinterpret_cast<float2*>(&sPh[(wrow + g + 8) * ASK + 8 * t + 2 * tg]) = h2;
            *reinterpret_cast<float2*>(&sPl[(wrow + g + 8) * ASK + 8 * t + 2 * tg]) = l2;
        }
        ps0 += __shfl_xor_sync(0xffffffffu, ps0, 1);
        ps0 += __shfl_xor_sync(0xffffffffu, ps0, 2);
        ps1 += __shfl_xor_sync(0xffffffffu, ps1, 1);
        ps1 += __shfl_xor_sync(0xffffffffu, ps1, 2);

        l0 = l0 * al0 + ps0;
        l1 = l1 * al1 + ps1;
        m0 = mn0;
        m1 = mn1;
        #pragma unroll
        for (int t = 0; t < 8; t++) {
            o[t][0] *= al0; o[t][1] *= al0;
            o[t][2] *= al1; o[t][3] *= al1;
        }
        __syncwarp();

        // O += P * V (3xTF32)
        #pragma unroll
        for (int kc = 0; kc < 8; kc++) {
            uint32_t ah[4], al_[4];
            const int pr0 = (wrow + g) * ASK + 8 * kc + tg;
            ah[0] = f2u(sPh[pr0]);               al_[0] = f2u(sPl[pr0]);
            ah[1] = f2u(sPh[pr0 + 8 * ASK]);     al_[1] = f2u(sPl[pr0 + 8 * ASK]);
            ah[2] = f2u(sPh[pr0 + 4]);           al_[2] = f2u(sPl[pr0 + 4]);
            ah[3] = f2u(sPh[pr0 + 8 * ASK + 4]); al_[3] = f2u(sPl[pr0 + 8 * ASK + 4]);
            #pragma unroll
            for (int t = 0; t < 8; t++) {
                const int i0 = (8 * kc + tg) * ASV + 8 * t + g;
                const int i1 = (8 * kc + tg + 4) * ASV + 8 * t + g;
                mma3(o[t], ah, al_,
                     f2u(sVh[i0]), f2u(sVl[i0]),
                     f2u(sVh[i1]), f2u(sVl[i1]));
            }
        }
        __syncthreads();
    }

    // Write unnormalized partials + m/l
    float* op = half ? g_op1 : g_op0;
    float* ml = half ? g_ml1 : g_ml0;
    const size_t row0 = (size_t)b * Sn + qbase + wrow + g;
    #pragma unroll
    for (int t = 0; t < 8; t++) {
        const int col = 8 * t + 2 * tg;
        float2 w0, w1;
        w0.x = o[t][0]; w0.y = o[t][1];
        w1.x = o[t][2]; w1.y = o[t][3];
        *reinterpret_cast<float2*>(&op[row0 * Hn + col]) = w0;
        *reinterpret_cast<float2*>(&op[(row0 + 8) * Hn + col]) = w1;
    }
    if (tg == 0) {
        ml[row0 * 2]           = m0;
        ml[row0 * 2 + 1]       = l0;
        ml[(row0 + 8) * 2]     = m1;
        ml[(row0 + 8) * 2 + 1] = l1;
    }
}

// ---------------------------------------------------------------------------
// Merge the two KV halves: out = (w0*o0 + w1*o1) / (w0*l0 + w1*l1)
// block 256 = 16 rows x 16 col-quads; grid = B*S/16
// ---------------------------------------------------------------------------
__global__ __launch_bounds__(256) void merge_kernel(float* __restrict__ out)
{
    const int tid = threadIdx.x;
    const int row = blockIdx.x * 16 + (tid >> 4);
    const int c4  = (tid & 15) * 4;

    const float m0 = g_ml0[row * 2],     l0 = g_ml0[row * 2 + 1];
    const float m1 = g_ml1[row * 2],     l1 = g_ml1[row * 2 + 1];
    const float m  = fmaxf(m0, m1);
    const float w0 = __expf(m0 - m);
    const float w1 = __expf(m1 - m);
    const float inv = 1.0f / (w0 * l0 + w1 * l1);

    float4 a = *reinterpret_cast<const float4*>(&g_op0[(size_t)row * Hn + c4]);
    float4 b = *reinterpret_cast<const float4*>(&g_op1[(size_t)row * Hn + c4]);
    float4 r;
    r.x = (w0 * a.x + w1 * b.x) * inv;
    r.y = (w0 * a.y + w1 * b.y) * inv;
    r.z = (w0 * a.z + w1 * b.z) * inv;
    r.w = (w0 * a.w + w1 * b.w) * inv;
    *reinterpret_cast<float4*>(&out[(size_t)row * Hn + c4]) = r;
}

extern "C" void kernel_launch(void* const* d_in, const int* in_sizes, int n_in,
                              void* d_out, int out_size)
{
    const float* x    = (const float*)d_in[0];
    const int*   mask = (const int*)d_in[1];
    const float* Wq   = (const float*)d_in[2];
    const float* bq   = (const float*)d_in[3];
    const float* Wk   = (const float*)d_in[4];
    const float* bk   = (const float*)d_in[5];
    const float* Wv   = (const float*)d_in[6];
    const float* bv   = (const float*)d_in[7];
    float* out = (float*)d_out;

    cudaFuncSetAttribute(proj_mma_kernel,
                         cudaFuncAttributeMaxDynamicSharedMemorySize,
                         PJ_TOT * (int)sizeof(float));
    cudaFuncSetAttribute(attn_mma_kernel,
                         cudaFuncAttributeMaxDynamicSharedMemorySize,
                         AT_TOT * (int)sizeof(float));

    proj_mma_kernel<<<Bn * Sn / 64, 256, PJ_TOT * sizeof(float)>>>(
        x, Wq, bq, Wk, bk, Wv, bv);

    dim3 gattn(Sn / 64, Bn, 2);
    attn_mma_kernel<<<gattn, 128, AT_TOT * sizeof(float)>>>(mask);

    merge_kernel<<<Bn * Sn / 16, 256>>>(out);
}

// round 7
// speedup vs baseline: 2.8906x; 1.2227x over previous
#include <cuda_runtime.h>
#include <math.h>
#include <cstdint>

#define Bn 8
#define Sn 2048
#define En 1024
#define Hn 64

// Scratch: q,k,v [B,S,H]; split-KV partials (unnormalized O + m/l per half)
__device__ float g_q[Bn * Sn * Hn];
__device__ float g_k[Bn * Sn * Hn];
__device__ float g_v[Bn * Sn * Hn];
__device__ float g_op0[Bn * Sn * Hn];
__device__ float g_op1[Bn * Sn * Hn];
__device__ float g_ml0[Bn * Sn * 2];
__device__ float g_ml1[Bn * Sn * 2];

// m16n8k16 bf16 mma: D += A*B, fp32 accumulate. regs hold bf16x2 pairs.
__device__ __forceinline__ void mma_bf16(float d[4], const uint32_t a[4],
                                         uint32_t b0, uint32_t b1)
{
    asm volatile(
        "mma.sync.aligned.m16n8k16.row.col.f32.bf16.bf16.f32 "
        "{%0,%1,%2,%3}, {%4,%5,%6,%7}, {%8,%9}, {%0,%1,%2,%3};"
        : "+f"(d[0]), "+f"(d[1]), "+f"(d[2]), "+f"(d[3])
        : "r"(a[0]), "r"(a[1]), "r"(a[2]), "r"(a[3]), "r"(b0), "r"(b1));
}

// Split a float pair into bf16x2 hi + bf16x2 residual. lo half = x0 (lower k).
__device__ __forceinline__ void split2(float x0, float x1,
                                       uint32_t& h, uint32_t& l)
{
    uint32_t hp;
    asm("cvt.rn.bf16x2.f32 %0, %1, %2;" : "=r"(hp) : "f"(x1), "f"(x0));
    float h0 = __uint_as_float(hp << 16);
    float h1 = __uint_as_float(hp & 0xffff0000u);
    uint32_t lp;
    asm("cvt.rn.bf16x2.f32 %0, %1, %2;" : "=r"(lp) : "f"(x1 - h1), "f"(x0 - h0));
    h = hp;
    l = lp;
}

// 3-term compensated bf16 MMA: d += a*b (hi*hi + hi*lo + lo*hi)
__device__ __forceinline__ void mma3(float d[4],
                                     const uint32_t ah[4], const uint32_t al[4],
                                     uint32_t bh0, uint32_t bl0,
                                     uint32_t bh1, uint32_t bl1)
{
    mma_bf16(d, ah, bh0, bh1);
    mma_bf16(d, ah, bl0, bl1);
    mma_bf16(d, al, bh0, bh1);
}

// ---------------------------------------------------------------------------
// Projection: [16384,1024] x [1024,192] (+bias) -> g_q|g_k|g_v
// CTA 64 rows x 192 cols, 8 warps (wm 0..3 row-group, wn 0..1 col-half).
// K-chunk 32 floats = 16 bf16x2 pairs. smem holds pre-split hi/lo pair tiles.
// X: [row][kp] stride 20; W: [n][kp] stride 20 (pairs cross W rows).
// ---------------------------------------------------------------------------
#define SXP 20
#define SWP 20
// u32 offsets in dynamic smem
#define PJ_XH 0
#define PJ_XL (PJ_XH + 64 * SXP)
#define PJ_WH (PJ_XL + 64 * SXP)
#define PJ_WL (PJ_WH + 192 * SWP)
#define PJ_B  (PJ_WL + 192 * SWP)
#define PJ_TOT (PJ_B + 192)

__global__ __launch_bounds__(256) void proj_mma_kernel(
    const float* __restrict__ x,
    const float* __restrict__ Wq, const float* __restrict__ bq,
    const float* __restrict__ Wk, const float* __restrict__ bk,
    const float* __restrict__ Wv, const float* __restrict__ bv)
{
    extern __shared__ uint32_t smu[];
    uint32_t* sXh = smu + PJ_XH;
    uint32_t* sXl = smu + PJ_XL;
    uint32_t* sWh = smu + PJ_WH;
    uint32_t* sWl = smu + PJ_WL;
    float*    sB  = (float*)(smu + PJ_B);

    const int tid  = threadIdx.x;
    const int warp = tid >> 5;
    const int lane = tid & 31;
    const int g    = lane >> 2;
    const int tg   = lane & 3;
    const int wm   = warp & 3;
    const int wn   = warp >> 2;
    const int row0 = blockIdx.x * 64;

    if (tid < 192)
        sB[tid] = (tid < 64) ? bq[tid] : (tid < 128 ? bk[tid - 64] : bv[tid - 128]);

    float acc[12][4];
    #pragma unroll
    for (int t = 0; t < 12; t++)
        #pragma unroll
        for (int i = 0; i < 4; i++) acc[t][i] = 0.0f;

    for (int k0 = 0; k0 < En; k0 += 32) {
        // X tile: 64 rows x 16 pairs (pairs along k, contiguous)
        #pragma unroll
        for (int u = 0; u < 2; u++) {
            int idx = tid + 256 * u;
            int r = idx >> 3, c = idx & 7;
            float4 v = *reinterpret_cast<const float4*>(
                &x[(size_t)(row0 + r) * En + k0 + 4 * c]);
            uint32_t h0, l0, h1, l1;
            split2(v.x, v.y, h0, l0);
            split2(v.z, v.w, h1, l1);
            uint2 hh; hh.x = h0; hh.y = h1;
            uint2 ll; ll.x = l0; ll.y = l1;
            *reinterpret_cast<uint2*>(&sXh[r * SXP + 2 * c]) = hh;
            *reinterpret_cast<uint2*>(&sXl[r * SXP + 2 * c]) = ll;
        }
        // W tile: 192 n-rows x 16 pairs (pairs along k: rows 2r,2r+1 of W)
        #pragma unroll
        for (int u = 0; u < 3; u++) {
            int idx = tid + 256 * u;      // < 768
            int r  = idx & 15;            // pair index (k/2)
            int nc = idx >> 4;            // 0..47 -> n = 4*nc
            int n  = 4 * nc;
            const float* Wm = (n < 64) ? Wq : (n < 128 ? Wk : Wv);
            const int lcol = n & 63;
            float4 va = *reinterpret_cast<const float4*>(
                &Wm[(size_t)(k0 + 2 * r) * Hn + lcol]);
            float4 vb = *reinterpret_cast<const float4*>(
                &Wm[(size_t)(k0 + 2 * r + 1) * Hn + lcol]);
            const float* fa = (const float*)&va;
            const float* fb = (const float*)&vb;
            #pragma unroll
            for (int j = 0; j < 4; j++) {
                uint32_t h, l;
                split2(fa[j], fb[j], h, l);
                sWh[(n + j) * SWP + r] = h;
                sWl[(n + j) * SWP + r] = l;
            }
        }
        __syncthreads();

        #pragma unroll
        for (int kk = 0; kk < 2; kk++) {   // two k16 windows per chunk
            uint32_t ah[4], al[4];
            const int ar0 = (16 * wm + g) * SXP + 8 * kk + tg;
            ah[0] = sXh[ar0];               al[0] = sXl[ar0];
            ah[1] = sXh[ar0 + 8 * SXP];     al[1] = sXl[ar0 + 8 * SXP];
            ah[2] = sXh[ar0 + 4];           al[2] = sXl[ar0 + 4];
            ah[3] = sXh[ar0 + 8 * SXP + 4]; al[3] = sXl[ar0 + 8 * SXP + 4];
            #pragma unroll
            for (int t = 0; t < 12; t++) {
                const int n  = wn * 96 + 8 * t + g;
                const int b0 = n * SWP + 8 * kk + tg;
                mma3(acc[t], ah, al,
                     sWh[b0], sWl[b0], sWh[b0 + 4], sWl[b0 + 4]);
            }
        }
        __syncthreads();
    }

    const int r0 = row0 + 16 * wm + g;
    #pragma unroll
    for (int t = 0; t < 12; t++) {
        const int col = wn * 96 + 8 * t + 2 * tg;
        float* dst = (col < 64) ? g_q : (col < 128 ? g_k : g_v);
        const int lcol = col & 63;
        float2 v0, v1;
        v0.x = acc[t][0] + sB[col];
        v0.y = acc[t][1] + sB[col + 1];
        v1.x = acc[t][2] + sB[col];
        v1.y = acc[t][3] + sB[col + 1];
        *reinterpret_cast<float2*>(&dst[(size_t)r0 * Hn + lcol]) = v0;
        *reinterpret_cast<float2*>(&dst[(size_t)(r0 + 8) * Hn + lcol]) = v1;
    }
}

// ---------------------------------------------------------------------------
// Flash attention, split-KV (2 halves), 3xBF16. CTA 64 q-rows, 4 warps.
// K: [n][hp] / V: [h][kvp] / P: [q][kvp], all stride 36 (bank-clean frags).
// grid (32, 8, 2), heavy q-tiles first.
// ---------------------------------------------------------------------------
#define SKP 36
#define AT_KH 0
#define AT_KL (AT_KH + 64 * SKP)
#define AT_VH (AT_KL + 64 * SKP)
#define AT_VL (AT_VH + 64 * SKP)
#define AT_PH (AT_VL + 64 * SKP)
#define AT_PL (AT_PH + 64 * SKP)
#define AT_M  (AT_PL + 64 * SKP)
#define AT_TOT (AT_M + 64)

__global__ __launch_bounds__(128) void attn_mma_kernel(
    const int* __restrict__ mask)
{
    extern __shared__ uint32_t smu[];
    uint32_t* sKh = smu + AT_KH;
    uint32_t* sKl = smu + AT_KL;
    uint32_t* sVh = smu + AT_VH;
    uint32_t* sVl = smu + AT_VL;
    uint32_t* sPh = smu + AT_PH;
    uint32_t* sPl = smu + AT_PL;
    float*    sM  = (float*)(smu + AT_M);

    const int b    = blockIdx.y;
    const int qt   = (gridDim.x - 1) - blockIdx.x;
    const int half = blockIdx.z;
    const int qbase = qt * 64;
    const int tid  = threadIdx.x;
    const int warp = tid >> 5;
    const int lane = tid & 31;
    const int g    = lane >> 2;
    const int tg   = lane & 3;
    const int wrow = warp * 16;

    const int nt  = qt + 1;
    const int nt0 = (nt + 1) >> 1;
    const int jt_begin = half ? nt0 : 0;
    const int jt_end   = half ? nt : nt0;

    const float* qp = g_q + ((size_t)b * Sn + qbase + wrow) * Hn;
    const float* kp = g_k + (size_t)b * Sn * Hn;
    const float* vp = g_v + (size_t)b * Sn * Hn;

    // Q fragments (pre-scaled by 0.125), persistent hi/lo pair splits
    uint32_t qh[4][4], ql[4][4];
    #pragma unroll
    for (int kc = 0; kc < 4; kc++) {
        const int kb = 16 * kc + 2 * tg;
        float2 q0 = *reinterpret_cast<const float2*>(&qp[(size_t)g * Hn + kb]);
        float2 q1 = *reinterpret_cast<const float2*>(&qp[(size_t)(g + 8) * Hn + kb]);
        float2 q2 = *reinterpret_cast<const float2*>(&qp[(size_t)g * Hn + kb + 8]);
        float2 q3 = *reinterpret_cast<const float2*>(&qp[(size_t)(g + 8) * Hn + kb + 8]);
        split2(q0.x * 0.125f, q0.y * 0.125f, qh[kc][0], ql[kc][0]);
        split2(q1.x * 0.125f, q1.y * 0.125f, qh[kc][1], ql[kc][1]);
        split2(q2.x * 0.125f, q2.y * 0.125f, qh[kc][2], ql[kc][2]);
        split2(q3.x * 0.125f, q3.y * 0.125f, qh[kc][3], ql[kc][3]);
    }

    float m0 = -1e30f, m1 = -1e30f, l0 = 0.0f, l1 = 0.0f;
    float o[8][4];
    #pragma unroll
    for (int t = 0; t < 8; t++)
        #pragma unroll
        for (int i = 0; i < 4; i++) o[t][i] = 0.0f;

    for (int jt = jt_begin; jt < jt_end; jt++) {
        const int kbase = jt * 64;

        // K tile: pairs along h (contiguous within row)
        #pragma unroll
        for (int u = 0; u < 8; u++) {
            int idx = tid + 128 * u;
            int r = idx >> 4, c = idx & 15;
            float4 kv = *reinterpret_cast<const float4*>(
                &kp[(size_t)(kbase + r) * Hn + 4 * c]);
            uint32_t h0, l0_, h1, l1_;
            split2(kv.x, kv.y, h0, l0_);
            split2(kv.z, kv.w, h1, l1_);
            uint2 hh; hh.x = h0; hh.y = h1;
            uint2 ll; ll.x = l0_; ll.y = l1_;
            *reinterpret_cast<uint2*>(&sKh[r * SKP + 2 * c]) = hh;
            *reinterpret_cast<uint2*>(&sKl[r * SKP + 2 * c]) = ll;
        }
        // V tile: transposed pair-pack (pairs along kv cross rows).
        // kvp-fast lane index -> conflict-free STS (LDG uncoalesced; L2 hits).
        #pragma unroll
        for (int u = 0; u < 4; u++) {
            int idx = tid + 128 * u;      // < 512
            int kvp = idx & 31;
            int c   = idx >> 5;           // 0..15, h = 4c..4c+3
            float4 va = *reinterpret_cast<const float4*>(
                &vp[(size_t)(kbase + 2 * kvp) * Hn + 4 * c]);
            float4 vb = *reinterpret_cast<const float4*>(
                &vp[(size_t)(kbase + 2 * kvp + 1) * Hn + 4 * c]);
            const float* fa = (const float*)&va;
            const float* fb = (const float*)&vb;
            #pragma unroll
            for (int j = 0; j < 4; j++) {
                uint32_t h, l;
                split2(fa[j], fb[j], h, l);
                sVh[(4 * c + j) * SKP + kvp] = h;
                sVl[(4 * c + j) * SKP + kvp] = l;
            }
        }
        if (tid < 64)
            sM[tid] = (mask[b * Sn + kbase + tid] != 0) ? 0.0f : -1e30f;
        __syncthreads();

        // S = Q * K^T (3xBF16, 4 k16 windows)
        float s[8][4];
        #pragma unroll
        for (int t = 0; t < 8; t++)
            #pragma unroll
            for (int i = 0; i < 4; i++) s[t][i] = 0.0f;

        #pragma unroll
        for (int t = 0; t < 8; t++) {
            const int krow = (8 * t + g) * SKP;
            #pragma unroll
            for (int kc = 0; kc < 4; kc++) {
                const int i0 = krow + 8 * kc + tg;
                mma3(s[t], qh[kc], ql[kc],
                     sKh[i0], sKl[i0], sKh[i0 + 4], sKl[i0 + 4]);
            }
        }

        // Mask + online softmax
        const bool diag = (jt == qt);
        const int lrow0 = wrow + g;
        float rmax0 = -1e30f, rmax1 = -1e30f;
        #pragma unroll
        for (int t = 0; t < 8; t++) {
            const int c = 8 * t + 2 * tg;
            const float pa0 = sM[c], pa1 = sM[c + 1];
            s[t][0] += pa0; s[t][1] += pa1;
            s[t][2] += pa0; s[t][3] += pa1;
            if (diag) {
                if (c > lrow0)         s[t][0] = -1e30f;
                if (c + 1 > lrow0)     s[t][1] = -1e30f;
                if (c > lrow0 + 8)     s[t][2] = -1e30f;
                if (c + 1 > lrow0 + 8) s[t][3] = -1e30f;
            }
            rmax0 = fmaxf(rmax0, fmaxf(s[t][0], s[t][1]));
            rmax1 = fmaxf(rmax1, fmaxf(s[t][2], s[t][3]));
        }
        rmax0 = fmaxf(rmax0, __shfl_xor_sync(0xffffffffu, rmax0, 1));
        rmax0 = fmaxf(rmax0, __shfl_xor_sync(0xffffffffu, rmax0, 2));
        rmax1 = fmaxf(rmax1, __shfl_xor_sync(0xffffffffu, rmax1, 1));
        rmax1 = fmaxf(rmax1, __shfl_xor_sync(0xffffffffu, rmax1, 2));

        const float mn0 = fmaxf(m0, rmax0);
        const float mn1 = fmaxf(m1, rmax1);
        const float al0 = __expf(m0 - mn0);
        const float al1 = __expf(m1 - mn1);

        float ps0 = 0.0f, ps1 = 0.0f;
        #pragma unroll
        for (int t = 0; t < 8; t++) {
            float p00 = __expf(s[t][0] - mn0);
            float p01 = __expf(s[t][1] - mn0);
            float p10 = __expf(s[t][2] - mn1);
            float p11 = __expf(s[t][3] - mn1);
            ps0 += p00 + p01;
            ps1 += p10 + p11;
            uint32_t h, l;
            split2(p00, p01, h, l);
            sPh[(wrow + g) * SKP + 4 * t + tg] = h;
            sPl[(wrow + g) * SKP + 4 * t + tg] = l;
            split2(p10, p11, h, l);
            sPh[(wrow + g + 8) * SKP + 4 * t + tg] = h;
            sPl[(wrow + g + 8) * SKP + 4 * t + tg] = l;
        }
        ps0 += __shfl_xor_sync(0xffffffffu, ps0, 1);
        ps0 += __shfl_xor_sync(0xffffffffu, ps0, 2);
        ps1 += __shfl_xor_sync(0xffffffffu, ps1, 1);
        ps1 += __shfl_xor_sync(0xffffffffu, ps1, 2);

        l0 = l0 * al0 + ps0;
        l1 = l1 * al1 + ps1;
        m0 = mn0;
        m1 = mn1;
        #pragma unroll
        for (int t = 0; t < 8; t++) {
            o[t][0] *= al0; o[t][1] *= al0;
            o[t][2] *= al1; o[t][3] *= al1;
        }
        __syncwarp();

        // O += P * V (3xBF16, 4 k16 windows over kv)
        #pragma unroll
        for (int kc = 0; kc < 4; kc++) {
            uint32_t ah[4], al_[4];
            const int pr = (wrow + g) * SKP + 8 * kc + tg;
            ah[0] = sPh[pr];               al_[0] = sPl[pr];
            ah[1] = sPh[pr + 8 * SKP];     al_[1] = sPl[pr + 8 * SKP];
            ah[2] = sPh[pr + 4];           al_[2] = sPl[pr + 4];
            ah[3] = sPh[pr + 8 * SKP + 4]; al_[3] = sPl[pr + 8 * SKP + 4];
            #pragma unroll
            for (int t = 0; t < 8; t++) {
                const int i0 = (8 * t + g) * SKP + 8 * kc + tg;
                mma3(o[t], ah, al_,
                     sVh[i0], sVl[i0], sVh[i0 + 4], sVl[i0 + 4]);
            }
        }
        __syncthreads();
    }

    // Write unnormalized partials + m/l
    float* op = half ? g_op1 : g_op0;
    float* ml = half ? g_ml1 : g_ml0;
    const size_t row0 = (size_t)b * Sn + qbase + wrow + g;
    #pragma unroll
    for (int t = 0; t < 8; t++) {
        const int col = 8 * t + 2 * tg;
        float2 w0, w1;
        w0.x = o[t][0]; w0.y = o[t][1];
        w1.x = o[t][2]; w1.y = o[t][3];
        *reinterpret_cast<float2*>(&op[row0 * Hn + col]) = w0;
        *reinterpret_cast<float2*>(&op[(row0 + 8) * Hn + col]) = w1;
    }
    if (tg == 0) {
        ml[row0 * 2]           = m0;
        ml[row0 * 2 + 1]       = l0;
        ml[(row0 + 8) * 2]     = m1;
        ml[(row0 + 8) * 2 + 1] = l1;
    }
}

// ---------------------------------------------------------------------------
// Merge the two KV halves: out = (w0*o0 + w1*o1) / (w0*l0 + w1*l1)
// ---------------------------------------------------------------------------
__global__ __launch_bounds__(256) void merge_kernel(float* __restrict__ out)
{
    const int tid = threadIdx.x;
    const int row = blockIdx.x * 16 + (tid >> 4);
    const int c4  = (tid & 15) * 4;

    const float m0 = g_ml0[row * 2],     l0 = g_ml0[row * 2 + 1];
    const float m1 = g_ml1[row * 2],     l1 = g_ml1[row * 2 + 1];
    const float m  = fmaxf(m0, m1);
    const float w0 = __expf(m0 - m);
    const float w1 = __expf(m1 - m);
    const float inv = 1.0f / (w0 * l0 + w1 * l1);

    float4 a = *reinterpret_cast<const float4*>(&g_op0[(size_t)row * Hn + c4]);
    float4 b = *reinterpret_cast<const float4*>(&g_op1[(size_t)row * Hn + c4]);
    float4 r;
    r.x = (w0 * a.x + w1 * b.x) * inv;
    r.y = (w0 * a.y + w1 * b.y) * inv;
    r.z = (w0 * a.z + w1 * b.z) * inv;
    r.w = (w0 * a.w + w1 * b.w) * inv;
    *reinterpret_cast<float4*>(&out[(size_t)row * Hn + c4]) = r;
}

extern "C" void kernel_launch(void* const* d_in, const int* in_sizes, int n_in,
                              void* d_out, int out_size)
{
    const float* x    = (const float*)d_in[0];
    const int*   mask = (const int*)d_in[1];
    const float* Wq   = (const float*)d_in[2];
    const float* bq   = (const float*)d_in[3];
    const float* Wk   = (const float*)d_in[4];
    const float* bk   = (const float*)d_in[5];
    const float* Wv   = (const float*)d_in[6];
    const float* bv   = (const float*)d_in[7];
    float* out = (float*)d_out;

    cudaFuncSetAttribute(proj_mma_kernel,
                         cudaFuncAttributeMaxDynamicSharedMemorySize,
                         PJ_TOT * (int)sizeof(uint32_t));
    cudaFuncSetAttribute(attn_mma_kernel,
                         cudaFuncAttributeMaxDynamicSharedMemorySize,
                         AT_TOT * (int)sizeof(uint32_t));

    proj_mma_kernel<<<Bn * Sn / 64, 256, PJ_TOT * sizeof(uint32_t)>>>(
        x, Wq, bq, Wk, bk, Wv, bv);

    dim3 gattn(Sn / 64, Bn, 2);
    attn_mma_kernel<<<gattn, 128, AT_TOT * sizeof(uint32_t)>>>(mask);

    merge_kernel<<<Bn * Sn / 16, 256>>>(out);
}